// round 11
// baseline (speedup 1.0000x reference)
#include <cuda_runtime.h>
#include <math.h>

// Problem constants
#define SQ   2048
#define BB   2
#define DD   1024
#define HH   16
#define DHH  64
#define WINW 256
#define MROWS (SQ*BB)   // 4096

// Scratch (device globals — no cudaMalloc allowed)
__device__ float g_q[BB*HH*SQ*DHH];    // 16 MB, head-major (z, s, dh)
__device__ float g_k[BB*HH*SQ*DHH];
__device__ float g_v[BB*HH*SQ*DHH];
__device__ float g_ctx[MROWS*DD];      // (s*B+b, D) row-major

// ---------------------------------------------------------------------------
// SGEMM: C(4096x1024) = A(4096x1024) @ W(1024x1024) + bias, templated epilogue
//   EPI 0: plain row-major store (O projection -> d_out)
//   EPI 1: scatter to head layout g_X[(b*H+h)*S + s][dh]
//   EPI 2: head layout + per-head q scale 0.125*exp(-beta[h])
// 128x128 block tile, BK=16, 8x8 per thread, double-buffered smem.
// ---------------------------------------------------------------------------
template<int EPI>
__global__ void __launch_bounds__(256, 2)
sgemm_kernel(const float* __restrict__ A, const float* __restrict__ W,
             const float* __restrict__ bias, const float* __restrict__ beta,
             float* __restrict__ C)
{
    constexpr int M = MROWS, N = DD, K = DD;
    __shared__ float As[2][16][128];   // transposed: As[k][m]
    __shared__ float Bs[2][16][128];   // Bs[k][n]

    const int tid = threadIdx.x;
    const int bm  = blockIdx.y * 128;
    const int bn  = blockIdx.x * 128;
    const int ty  = tid >> 4;          // 0..15
    const int tx  = tid & 15;          // 0..15

    const int arow = tid >> 2;         // 0..63 (+64)
    const int acol = (tid & 3) * 4;    // 0,4,8,12
    const int brow = tid >> 5;         // 0..7 (+8)
    const int bcol = (tid & 31) * 4;   // 0..124

    float acc[8][8];
    #pragma unroll
    for (int i = 0; i < 8; i++)
        #pragma unroll
        for (int j = 0; j < 8; j++) acc[i][j] = 0.f;

    // prologue: tile kt=0 into buffer 0
    #pragma unroll
    for (int r = 0; r < 2; r++) {
        int row = arow + r * 64;
        float4 va = *(const float4*)(A + (size_t)(bm + row) * K + acol);
        As[0][acol + 0][row] = va.x;
        As[0][acol + 1][row] = va.y;
        As[0][acol + 2][row] = va.z;
        As[0][acol + 3][row] = va.w;
    }
    #pragma unroll
    for (int r = 0; r < 2; r++) {
        int row = brow + r * 8;
        *(float4*)&Bs[0][row][bcol] =
            *(const float4*)(W + (size_t)row * N + bn + bcol);
    }
    __syncthreads();

    int buf = 0;
    for (int kt = 0; kt < K; kt += 16) {
        if (kt + 16 < K) {
            #pragma unroll
            for (int r = 0; r < 2; r++) {
                int row = arow + r * 64;
                float4 va = *(const float4*)(A + (size_t)(bm + row) * K + (kt + 16) + acol);
                As[buf ^ 1][acol + 0][row] = va.x;
                As[buf ^ 1][acol + 1][row] = va.y;
                As[buf ^ 1][acol + 2][row] = va.z;
                As[buf ^ 1][acol + 3][row] = va.w;
            }
            #pragma unroll
            for (int r = 0; r < 2; r++) {
                int row = brow + r * 8;
                *(float4*)&Bs[buf ^ 1][row][bcol] =
                    *(const float4*)(W + (size_t)(kt + 16 + row) * N + bn + bcol);
            }
        }
        #pragma unroll
        for (int kk = 0; kk < 16; kk++) {
            float a[8], b[8];
            *(float4*)&a[0] = *(const float4*)&As[buf][kk][ty * 8];
            *(float4*)&a[4] = *(const float4*)&As[buf][kk][ty * 8 + 4];
            *(float4*)&b[0] = *(const float4*)&Bs[buf][kk][tx * 8];
            *(float4*)&b[4] = *(const float4*)&Bs[buf][kk][tx * 8 + 4];
            #pragma unroll
            for (int i = 0; i < 8; i++)
                #pragma unroll
                for (int j = 0; j < 8; j++)
                    acc[i][j] += a[i] * b[j];
        }
        __syncthreads();
        buf ^= 1;
    }

    // epilogue
    #pragma unroll
    for (int i = 0; i < 8; i++) {
        const int row = bm + ty * 8 + i;
        #pragma unroll
        for (int j = 0; j < 8; j++) {
            const int col = bn + tx * 8 + j;
            float val = acc[i][j] + bias[col];
            if (EPI == 0) {
                C[(size_t)row * N + col] = val;
            } else {
                const int s  = row >> 1;
                const int b  = row & 1;
                const int h  = col >> 6;
                const int dh = col & 63;
                if (EPI == 2) val *= 0.125f * __expf(-beta[h]);
                C[(((size_t)(b * HH + h)) * SQ + s) * DHH + dh] = val;
            }
        }
    }
}

// ---------------------------------------------------------------------------
// Attention: one block per (z, 64-query tile). Window fits in smem.
//   Ksm: 320 keys x 64 dims, stride 65 (conflict-free). Vsm: 320x64 stride 64.
//   Scores in registers (8q x 10k per lane), softmax + sink via shuffles,
//   P matrix reuses Ksm region for the P@V pass.
// ---------------------------------------------------------------------------
__global__ void __launch_bounds__(256, 1)
attn_kernel(const float* __restrict__ Q, const float* __restrict__ K,
            const float* __restrict__ V, float* __restrict__ ctx)
{
    extern __shared__ float sm[];
    float* Ksm = sm;                          // 320*65 = 20800 floats
    float* Vsm = sm + 320 * 65;               // 320*64 = 20480 floats
    float* Qsm = sm + 320 * 65 + 320 * 64;    // 64*64  = 4096 floats
    float* Psm = sm;                          // alias Ksm: 64*320 = 20480 floats

    const int tid   = threadIdx.x;
    const int z     = blockIdx.y;             // b*H + h
    const int q0    = blockIdx.x * 64;
    const int kbase = q0 - 256;
    const size_t base = (size_t)z * SQ * DHH;

    // --- load Q tile (float4) ---
    #pragma unroll
    for (int t = 0; t < 4; t++) {
        int i4 = tid + t * 256;               // 0..1023 float4 slots
        int qi = i4 >> 4;
        int d4 = (i4 & 15) * 4;
        *(float4*)&Qsm[qi * 64 + d4] =
            *(const float4*)&Q[base + (size_t)(q0 + qi) * DHH + d4];
    }
    // --- load K window (scalar into padded stride 65) ---
    for (int idx = tid; idx < 320 * 64; idx += 256) {
        int j = idx >> 6, d = idx & 63;
        int kp = kbase + j;
        Ksm[j * 65 + d] = (kp >= 0) ? K[base + (size_t)kp * DHH + d] : 0.f;
    }
    // --- load V window (float4) ---
    #pragma unroll
    for (int t = 0; t < 20; t++) {
        int i4 = tid + t * 256;               // 0..5119
        int j  = i4 >> 4;
        int d4 = (i4 & 15) * 4;
        int kp = kbase + j;
        float4 vv = make_float4(0.f, 0.f, 0.f, 0.f);
        if (kp >= 0) vv = *(const float4*)&V[base + (size_t)kp * DHH + d4];
        *(float4*)&Vsm[j * 64 + d4] = vv;
    }
    __syncthreads();

    // --- phase 2: scores (8 queries per warp, 10 keys per lane) ---
    const int w = tid >> 5, lane = tid & 31;
    float acc[8][10];
    #pragma unroll
    for (int i = 0; i < 8; i++)
        #pragma unroll
        for (int j = 0; j < 10; j++) acc[i][j] = 0.f;

    const float* qrow = Qsm + (w * 8) * 64;
    #pragma unroll 4
    for (int d = 0; d < 64; d++) {
        float qv[8];
        #pragma unroll
        for (int i = 0; i < 8; i++) qv[i] = qrow[i * 64 + d];
        float kv[10];
        #pragma unroll
        for (int j = 0; j < 10; j++) kv[j] = Ksm[(lane + 32 * j) * 65 + d];
        #pragma unroll
        for (int i = 0; i < 8; i++)
            #pragma unroll
            for (int j = 0; j < 10; j++)
                acc[i][j] += qv[i] * kv[j];
    }

    // --- softmax with sink (zero logit) per query ---
    #pragma unroll
    for (int i = 0; i < 8; i++) {
        const int qloc = w * 8 + i;
        float m = 0.f;  // sink logit = 0 included in the max
        #pragma unroll
        for (int j = 0; j < 10; j++) {
            int jj = lane + 32 * j;
            // allowed: 1 <= (q - k) <= 256 handled as jj in (qloc, qloc+256],
            // self (diff=0) is jj == qloc+256; also key position >= 0
            bool ok = (jj > qloc) && (jj <= qloc + 256) && (kbase + jj >= 0);
            if (!ok) acc[i][j] = -1e30f;
            m = fmaxf(m, acc[i][j]);
        }
        #pragma unroll
        for (int off = 16; off > 0; off >>= 1)
            m = fmaxf(m, __shfl_xor_sync(0xffffffffu, m, off));
        float ssum = 0.f;
        #pragma unroll
        for (int j = 0; j < 10; j++) {
            float p = (acc[i][j] > -1e29f) ? __expf(acc[i][j] - m) : 0.f;
            acc[i][j] = p;
            ssum += p;
        }
        #pragma unroll
        for (int off = 16; off > 0; off >>= 1)
            ssum += __shfl_xor_sync(0xffffffffu, ssum, off);
        const float inv = 1.f / (ssum + __expf(-m));   // + sink mass
        #pragma unroll
        for (int j = 0; j < 10; j++) acc[i][j] *= inv;
    }

    __syncthreads();   // all warps done reading Ksm — safe to overwrite with P
    #pragma unroll
    for (int i = 0; i < 8; i++)
        #pragma unroll
        for (int j = 0; j < 10; j++)
            Psm[(w * 8 + i) * 320 + lane + 32 * j] = acc[i][j];
    __syncthreads();

    // --- phase 3: O = P @ V. Thread owns dim d, 16 queries strided by 4 ---
    const int d  = tid & 63;
    const int qg = tid >> 6;   // 0..3
    float o[16];
    #pragma unroll
    for (int t = 0; t < 16; t++) o[t] = 0.f;
    #pragma unroll 2
    for (int k = 0; k < 320; k++) {
        float vv = Vsm[k * 64 + d];
        #pragma unroll
        for (int t = 0; t < 16; t++)
            o[t] += Psm[(qg + 4 * t) * 320 + k] * vv;
    }
    const int b = z >> 4, h = z & 15;
    #pragma unroll
    for (int t = 0; t < 16; t++) {
        const int qi = qg + 4 * t;
        ctx[((size_t)(q0 + qi) * BB + b) * DD + h * DHH + d] = o[t];
    }
}

// ---------------------------------------------------------------------------
extern "C" void kernel_launch(void* const* d_in, const int* in_sizes, int n_in,
                              void* d_out, int out_size)
{
    const float* x    = (const float*)d_in[0];
    const float* beta = (const float*)d_in[1];
    const float* Wq   = (const float*)d_in[2];
    const float* bq   = (const float*)d_in[3];
    const float* Wk   = (const float*)d_in[4];
    const float* bk   = (const float*)d_in[5];
    const float* Wv   = (const float*)d_in[6];
    const float* bv   = (const float*)d_in[7];
    const float* Wo   = (const float*)d_in[8];
    const float* bo   = (const float*)d_in[9];
    float* out = (float*)d_out;

    float *q, *k, *v, *ctx;
    cudaGetSymbolAddress((void**)&q,   g_q);
    cudaGetSymbolAddress((void**)&k,   g_k);
    cudaGetSymbolAddress((void**)&v,   g_v);
    cudaGetSymbolAddress((void**)&ctx, g_ctx);

    const dim3 gg(DD / 128, MROWS / 128);   // (8, 32)

    // QKV projections with fused head-layout scatter (+ q temperature scale)
    sgemm_kernel<2><<<gg, 256>>>(x, Wq, bq, beta, q);
    sgemm_kernel<1><<<gg, 256>>>(x, Wk, bk, nullptr, k);
    sgemm_kernel<1><<<gg, 256>>>(x, Wv, bv, nullptr, v);

    // Windowed attention with sink
    const size_t ATTN_SMEM = (size_t)(320 * 65 + 320 * 64 + 64 * 64) * sizeof(float);
    cudaFuncSetAttribute(attn_kernel, cudaFuncAttributeMaxDynamicSharedMemorySize,
                         (int)ATTN_SMEM);
    attn_kernel<<<dim3(SQ / 64, BB * HH), 256, ATTN_SMEM>>>(q, k, v, ctx);

    // Output projection straight into d_out
    sgemm_kernel<0><<<gg, 256>>>(ctx, Wo, bo, nullptr, out);
}

// round 14
// speedup vs baseline: 1.8044x; 1.8044x over previous
#include <cuda_runtime.h>
#include <cuda_bf16.h>
#include <cstdint>
#include <math.h>

// Problem constants
#define SQ   2048
#define BB   2
#define DD   1024
#define HH   16
#define DHH  64
#define MROWS (SQ*BB)   // 4096

// ---------------------------------------------------------------------------
// Device scratch (no cudaMalloc allowed)
// ---------------------------------------------------------------------------
__device__ __nv_bfloat16 g_xhi[MROWS*DD];
__device__ __nv_bfloat16 g_xlo[MROWS*DD];
__device__ __nv_bfloat16 g_wthi[4][DD*DD];   // W^T as [N][K], bf16 hi
__device__ __nv_bfloat16 g_wtlo[4][DD*DD];   // bf16 lo
__device__ float g_q[BB*HH*SQ*DHH];
__device__ float g_k[BB*HH*SQ*DHH];
__device__ float g_v[BB*HH*SQ*DHH];
__device__ __nv_bfloat16 g_chi[MROWS*DD];
__device__ __nv_bfloat16 g_clo[MROWS*DD];

// ---------------------------------------------------------------------------
// PTX helpers (sm_80-class features only — NO tcgen05 / 'a'-features)
// ---------------------------------------------------------------------------
__device__ __forceinline__ uint32_t smem_to_u32(const void* p) {
    uint32_t a;
    asm("{ .reg .u64 t; cvta.to.shared.u64 t, %1; cvt.u32.u64 %0, t; }"
        : "=r"(a) : "l"(p));
    return a;
}

#define CP_ASYNC16(dst, src) \
    asm volatile("cp.async.cg.shared.global [%0], [%1], 16;" \
        :: "r"(dst), "l"(src) : "memory")
#define CP_COMMIT() asm volatile("cp.async.commit_group;" ::: "memory")
#define CP_WAIT0()  asm volatile("cp.async.wait_group 0;" ::: "memory")

#define LDSM_X4(r0, r1, r2, r3, addr) \
    asm volatile("ldmatrix.sync.aligned.m8n8.x4.shared.b16 {%0,%1,%2,%3}, [%4];" \
        : "=r"(r0), "=r"(r1), "=r"(r2), "=r"(r3) : "r"(addr))

#define MMA_BF16(c, a0, a1, a2, a3, b0, b1) \
    asm volatile("mma.sync.aligned.m16n8k16.row.col.f32.bf16.bf16.f32 " \
        "{%0,%1,%2,%3}, {%4,%5,%6,%7}, {%8,%9}, {%0,%1,%2,%3};" \
        : "+f"((c)[0]), "+f"((c)[1]), "+f"((c)[2]), "+f"((c)[3]) \
        : "r"(a0), "r"(a1), "r"(a2), "r"(a3), "r"(b0), "r"(b1))

// ---------------------------------------------------------------------------
// Prep kernels
// ---------------------------------------------------------------------------
__global__ void convert_split_kernel(const float* __restrict__ x,
                                     __nv_bfloat16* __restrict__ hi,
                                     __nv_bfloat16* __restrict__ lo, int n)
{
    int i = blockIdx.x * blockDim.x + threadIdx.x;
    if (i < n) {
        float v = x[i];
        __nv_bfloat16 h = __float2bfloat16(v);
        hi[i] = h;
        lo[i] = __float2bfloat16(v - __bfloat162float(h));
    }
}

// W [K=1024][N=1024] fp32 -> Wt_hi/lo [N][K] bf16
__global__ void transpose_split_kernel(const float* __restrict__ W,
                                       __nv_bfloat16* __restrict__ Thi,
                                       __nv_bfloat16* __restrict__ Tlo)
{
    __shared__ float t[32][33];
    const int k0 = blockIdx.y * 32, n0 = blockIdx.x * 32;
    const int tx = threadIdx.x, ty = threadIdx.y;
    #pragma unroll
    for (int j = 0; j < 32; j += 8)
        t[ty + j][tx] = W[(size_t)(k0 + ty + j) * DD + n0 + tx];
    __syncthreads();
    #pragma unroll
    for (int j = 0; j < 32; j += 8) {
        float v = t[tx][ty + j];
        __nv_bfloat16 h = __float2bfloat16(v);
        size_t o = (size_t)(n0 + ty + j) * DD + k0 + tx;
        Thi[o] = h;
        Tlo[o] = __float2bfloat16(v - __bfloat162float(h));
    }
}

// ---------------------------------------------------------------------------
// mma.sync bf16x3 GEMM: C(4096x1024) = A @ B^T
//   A [M][K] bf16 hi/lo, B [N][K] bf16 hi/lo (transposed weights).
//   CTA tile 128x256, BK=32, 8 warps (2M x 4N) each 64x64.
//   3 products: Ahi*Bhi + Ahi*Blo + Alo*Bhi  (fp32 accumulate)
//   EPI 0: row-major + bias; EPI 1: head scatter + bias; EPI 2: + q scale
// ---------------------------------------------------------------------------
#define BKC      32
#define NCH      (DD / BKC)       // 32
#define A_BYTES  10240            // 128 rows * 80B (padded)
#define B_BYTES  20480            // 256 rows * 80B
#define STG_BYTES (2*A_BYTES + 2*B_BYTES)   // 61440
#define GEMM_SMEM (2 * STG_BYTES)           // 122880

template<int EPI>
__global__ void __launch_bounds__(256, 1)
gemm_mma(const __nv_bfloat16* __restrict__ Ahi, const __nv_bfloat16* __restrict__ Alo,
         const __nv_bfloat16* __restrict__ Bhi, const __nv_bfloat16* __restrict__ Blo,
         const float* __restrict__ bias, const float* __restrict__ beta,
         float* __restrict__ C)
{
    extern __shared__ char smem[];
    const uint32_t sb = smem_to_u32(smem);
    const int tid  = threadIdx.x;
    const int lane = tid & 31;
    const int w    = tid >> 5;
    const int wm   = w & 1;          // 2 warps in M
    const int wn   = w >> 1;         // 4 warps in N
    const int bm = blockIdx.y * 128;
    const int bn = blockIdx.x * 256;
    const int m0w = wm * 64;
    const int n0w = wn * 64;

    float c[4][8][4];
    #pragma unroll
    for (int mi = 0; mi < 4; mi++)
        #pragma unroll
        for (int ni = 0; ni < 8; ni++)
            #pragma unroll
            for (int r = 0; r < 4; r++) c[mi][ni][r] = 0.f;

    auto load_chunk = [&](int ch, int s) {
        const int kt = ch * BKC;
        const uint32_t base = sb + s * STG_BYTES;
        // A: 128 rows x 32 bf16 = 4 x uint4 per row (hi & lo)
        #pragma unroll
        for (int i = tid; i < 512; i += 256) {
            int r = i >> 2, g = i & 3;
            uint32_t off = (uint32_t)(r * 80 + g * 16);
            const char* ph = (const char*)(Ahi + (size_t)(bm + r) * DD + kt) + g * 16;
            const char* pl = (const char*)(Alo + (size_t)(bm + r) * DD + kt) + g * 16;
            CP_ASYNC16(base + off, ph);
            CP_ASYNC16(base + A_BYTES + off, pl);
        }
        // B: 256 rows
        #pragma unroll
        for (int i = tid; i < 1024; i += 256) {
            int r = i >> 2, g = i & 3;
            uint32_t off = (uint32_t)(r * 80 + g * 16);
            const char* ph = (const char*)(Bhi + (size_t)(bn + r) * DD + kt) + g * 16;
            const char* pl = (const char*)(Blo + (size_t)(bn + r) * DD + kt) + g * 16;
            CP_ASYNC16(base + 2 * A_BYTES + off, ph);
            CP_ASYNC16(base + 2 * A_BYTES + B_BYTES + off, pl);
        }
        CP_COMMIT();
    };

    // per-lane ldmatrix offset parts (same pattern for A and B, non-trans):
    // row = tile_row0 + (lane & 15), kcol = ks + (lane>>4)*8
    const uint32_t lrow = (uint32_t)(lane & 15);
    const uint32_t lk   = (uint32_t)((lane >> 4) << 3);

    load_chunk(0, 0);
    CP_WAIT0();
    __syncthreads();

    for (int ch = 0; ch < NCH; ch++) {
        const int s = ch & 1;
        if (ch + 1 < NCH) load_chunk(ch + 1, s ^ 1);

        const uint32_t base = sb + s * STG_BYTES;
        #pragma unroll
        for (int ks = 0; ks < BKC; ks += 16) {
            uint32_t bh[4][4], bl[4][4];
            #pragma unroll
            for (int np = 0; np < 4; np++) {
                uint32_t ba = base + 2 * A_BYTES +
                    (uint32_t)(((n0w + np * 16 + lrow) * 40 + ks) * 2) + lk * 2;
                LDSM_X4(bh[np][0], bh[np][1], bh[np][2], bh[np][3], ba);
                LDSM_X4(bl[np][0], bl[np][1], bl[np][2], bl[np][3], ba + B_BYTES);
            }
            #pragma unroll
            for (int mi = 0; mi < 4; mi++) {
                uint32_t aa = base +
                    (uint32_t)(((m0w + mi * 16 + lrow) * 40 + ks) * 2) + lk * 2;
                uint32_t ah[4], al[4];
                LDSM_X4(ah[0], ah[1], ah[2], ah[3], aa);
                LDSM_X4(al[0], al[1], al[2], al[3], aa + A_BYTES);
                #pragma unroll
                for (int np = 0; np < 4; np++) {
                    // n-tile 2*np uses regs (x[np][0], x[np][2]); 2*np+1 uses ([1],[3])
                    MMA_BF16(c[mi][2*np],   ah[0], ah[1], ah[2], ah[3], bh[np][0], bh[np][2]);
                    MMA_BF16(c[mi][2*np],   ah[0], ah[1], ah[2], ah[3], bl[np][0], bl[np][2]);
                    MMA_BF16(c[mi][2*np],   al[0], al[1], al[2], al[3], bh[np][0], bh[np][2]);
                    MMA_BF16(c[mi][2*np+1], ah[0], ah[1], ah[2], ah[3], bh[np][1], bh[np][3]);
                    MMA_BF16(c[mi][2*np+1], ah[0], ah[1], ah[2], ah[3], bl[np][1], bl[np][3]);
                    MMA_BF16(c[mi][2*np+1], al[0], al[1], al[2], al[3], bh[np][1], bh[np][3]);
                }
            }
        }
        if (ch + 1 < NCH) CP_WAIT0();
        __syncthreads();
    }

    // Epilogue: fragment (mi,ni): rows m0+mi*16+lane/4 (+8), cols n0+ni*8+(lane%4)*2
    #pragma unroll
    for (int mi = 0; mi < 4; mi++) {
        #pragma unroll
        for (int ni = 0; ni < 8; ni++) {
            const int row = bm + m0w + mi * 16 + (lane >> 2);
            const int col = bn + n0w + ni * 8 + (lane & 3) * 2;
            const float b0 = __ldg(&bias[col]);
            const float b1 = __ldg(&bias[col + 1]);
            const float* cc = c[mi][ni];
            if (EPI == 0) {
                float2 v0 = make_float2(cc[0] + b0, cc[1] + b1);
                float2 v1 = make_float2(cc[2] + b0, cc[3] + b1);
                *(float2*)&C[(size_t)row * DD + col] = v0;
                *(float2*)&C[(size_t)(row + 8) * DD + col] = v1;
            } else {
                const int h  = col >> 6;
                const int dh = col & 63;
                const float sc = (EPI == 2) ? 0.125f * __expf(-__ldg(&beta[h])) : 1.0f;
                // row r -> s = r>>1, b = r&1; out[(b*H+h)*S + s][dh]
                {
                    const int srow = row >> 1, brow = row & 1;
                    float2 v = make_float2((cc[0] + b0) * sc, (cc[1] + b1) * sc);
                    *(float2*)&C[(((size_t)(brow * HH + h)) * SQ + srow) * DHH + dh] = v;
                }
                {
                    const int r2 = row + 8;
                    const int srow = r2 >> 1, brow = r2 & 1;
                    float2 v = make_float2((cc[2] + b0) * sc, (cc[3] + b1) * sc);
                    *(float2*)&C[(((size_t)(brow * HH + h)) * SQ + srow) * DHH + dh] = v;
                }
            }
        }
    }
}

// ---------------------------------------------------------------------------
// Attention: K in smem (padded), V streamed from L2, P aliases K region.
// smem = 320*65 + 64*64 floats = 99584 B -> 2 CTAs/SM.
// ---------------------------------------------------------------------------
__global__ void __launch_bounds__(256, 2)
attn_kernel(const float* __restrict__ Q, const float* __restrict__ K,
            const float* __restrict__ V,
            __nv_bfloat16* __restrict__ Chi, __nv_bfloat16* __restrict__ Clo)
{
    extern __shared__ float sm[];
    float* Ksm = sm;                 // 320*65 = 20800 floats
    float* Qsm = sm + 320 * 65;      // 64*64  = 4096 floats
    float* Psm = sm;                 // alias Ksm: 64*320 = 20480 floats

    const int tid   = threadIdx.x;
    const int z     = blockIdx.y;
    const int q0    = blockIdx.x * 64;
    const int kbase = q0 - 256;
    const size_t base = (size_t)z * SQ * DHH;

    #pragma unroll
    for (int t = 0; t < 4; t++) {
        int i4 = tid + t * 256;
        int qi = i4 >> 4;
        int d4 = (i4 & 15) * 4;
        *(float4*)&Qsm[qi * 64 + d4] =
            *(const float4*)&Q[base + (size_t)(q0 + qi) * DHH + d4];
    }
    for (int idx = tid; idx < 320 * 64; idx += 256) {
        int j = idx >> 6, d = idx & 63;
        int kp = kbase + j;
        Ksm[j * 65 + d] = (kp >= 0) ? K[base + (size_t)kp * DHH + d] : 0.f;
    }
    __syncthreads();

    const int w = tid >> 5, lane = tid & 31;
    float acc[8][10];
    #pragma unroll
    for (int i = 0; i < 8; i++)
        #pragma unroll
        for (int j = 0; j < 10; j++) acc[i][j] = 0.f;

    const float* qrow = Qsm + (w * 8) * 64;
    #pragma unroll 4
    for (int d = 0; d < 64; d++) {
        float qv[8];
        #pragma unroll
        for (int i = 0; i < 8; i++) qv[i] = qrow[i * 64 + d];
        float kv[10];
        #pragma unroll
        for (int j = 0; j < 10; j++) kv[j] = Ksm[(lane + 32 * j) * 65 + d];
        #pragma unroll
        for (int i = 0; i < 8; i++)
            #pragma unroll
            for (int j = 0; j < 10; j++)
                acc[i][j] += qv[i] * kv[j];
    }

    #pragma unroll
    for (int i = 0; i < 8; i++) {
        const int qloc = w * 8 + i;
        float m = 0.f;   // sink logit 0 included in max
        #pragma unroll
        for (int j = 0; j < 10; j++) {
            int jj = lane + 32 * j;
            bool ok = (jj > qloc) && (jj <= qloc + 256) && (kbase + jj >= 0);
            if (!ok) acc[i][j] = -1e30f;
            m = fmaxf(m, acc[i][j]);
        }
        #pragma unroll
        for (int off = 16; off > 0; off >>= 1)
            m = fmaxf(m, __shfl_xor_sync(0xffffffffu, m, off));
        float ssum = 0.f;
        #pragma unroll
        for (int j = 0; j < 10; j++) {
            float p = (acc[i][j] > -1e29f) ? __expf(acc[i][j] - m) : 0.f;
            acc[i][j] = p;
            ssum += p;
        }
        #pragma unroll
        for (int off = 16; off > 0; off >>= 1)
            ssum += __shfl_xor_sync(0xffffffffu, ssum, off);
        const float inv = 1.f / (ssum + __expf(-m));   // + sink mass
        #pragma unroll
        for (int j = 0; j < 10; j++) acc[i][j] *= inv;
    }

    __syncthreads();   // all warps done reading Ksm
    #pragma unroll
    for (int i = 0; i < 8; i++)
        #pragma unroll
        for (int j = 0; j < 10; j++)
            Psm[(w * 8 + i) * 320 + lane + 32 * j] = acc[i][j];
    __syncthreads();

    // O = P @ V, V streamed from global (L2-resident). Masked P entries are 0.
    const int d  = tid & 63;
    const int qg = tid >> 6;
    const float* Vz = V + base;
    float o[16];
    #pragma unroll
    for (int t = 0; t < 16; t++) o[t] = 0.f;
    #pragma unroll 4
    for (int k = 0; k < 320; k++) {
        int kp = kbase + k;
        int kc = kp < 0 ? 0 : kp;
        float vv = __ldg(&Vz[(size_t)kc * DHH + d]);
        #pragma unroll
        for (int t = 0; t < 16; t++)
            o[t] += Psm[(qg + 4 * t) * 320 + k] * vv;
    }
    const int b = z >> 4, h = z & 15;
    #pragma unroll
    for (int t = 0; t < 16; t++) {
        const int qi = qg + 4 * t;
        const size_t idx = ((size_t)(q0 + qi) * BB + b) * DD + h * DHH + d;
        const float val = o[t];
        __nv_bfloat16 hi = __float2bfloat16(val);
        Chi[idx] = hi;
        Clo[idx] = __float2bfloat16(val - __bfloat162float(hi));
    }
}

// ---------------------------------------------------------------------------
extern "C" void kernel_launch(void* const* d_in, const int* in_sizes, int n_in,
                              void* d_out, int out_size)
{
    const float* x    = (const float*)d_in[0];
    const float* beta = (const float*)d_in[1];
    const float* Wq   = (const float*)d_in[2];
    const float* bq   = (const float*)d_in[3];
    const float* Wk   = (const float*)d_in[4];
    const float* bk   = (const float*)d_in[5];
    const float* Wv   = (const float*)d_in[6];
    const float* bv   = (const float*)d_in[7];
    const float* Wo   = (const float*)d_in[8];
    const float* bo   = (const float*)d_in[9];
    float* out = (float*)d_out;

    __nv_bfloat16 *xhi, *xlo, *wthi, *wtlo, *chi, *clo;
    float *q, *k, *v;
    cudaGetSymbolAddress((void**)&xhi,  g_xhi);
    cudaGetSymbolAddress((void**)&xlo,  g_xlo);
    cudaGetSymbolAddress((void**)&wthi, g_wthi);
    cudaGetSymbolAddress((void**)&wtlo, g_wtlo);
    cudaGetSymbolAddress((void**)&q,    g_q);
    cudaGetSymbolAddress((void**)&k,    g_k);
    cudaGetSymbolAddress((void**)&v,    g_v);
    cudaGetSymbolAddress((void**)&chi,  g_chi);
    cudaGetSymbolAddress((void**)&clo,  g_clo);

    // --- prep: split x, transpose+split weights ---
    convert_split_kernel<<<(MROWS * DD + 255) / 256, 256>>>(x, xhi, xlo, MROWS * DD);
    const float* Ws[4] = { Wq, Wk, Wv, Wo };
    for (int i = 0; i < 4; i++)
        transpose_split_kernel<<<dim3(32, 32), dim3(32, 8)>>>(
            Ws[i], wthi + (size_t)i * DD * DD, wtlo + (size_t)i * DD * DD);

    // --- mma.sync GEMMs ---
    cudaFuncSetAttribute(gemm_mma<0>, cudaFuncAttributeMaxDynamicSharedMemorySize, GEMM_SMEM);
    cudaFuncSetAttribute(gemm_mma<1>, cudaFuncAttributeMaxDynamicSharedMemorySize, GEMM_SMEM);
    cudaFuncSetAttribute(gemm_mma<2>, cudaFuncAttributeMaxDynamicSharedMemorySize, GEMM_SMEM);
    const dim3 gg(DD / 256, MROWS / 128);   // (4, 32) = 128 CTAs

    gemm_mma<2><<<gg, 256, GEMM_SMEM>>>(xhi, xlo,
        wthi + 0 * (size_t)DD * DD, wtlo + 0 * (size_t)DD * DD, bq, beta, q);
    gemm_mma<1><<<gg, 256, GEMM_SMEM>>>(xhi, xlo,
        wthi + 1 * (size_t)DD * DD, wtlo + 1 * (size_t)DD * DD, bk, nullptr, k);
    gemm_mma<1><<<gg, 256, GEMM_SMEM>>>(xhi, xlo,
        wthi + 2 * (size_t)DD * DD, wtlo + 2 * (size_t)DD * DD, bv, nullptr, v);

    // --- attention ---
    const int ATTN_SMEM = (320 * 65 + 64 * 64) * (int)sizeof(float);   // 99584
    cudaFuncSetAttribute(attn_kernel, cudaFuncAttributeMaxDynamicSharedMemorySize, ATTN_SMEM);
    attn_kernel<<<dim3(SQ / 64, BB * HH), 256, ATTN_SMEM>>>(q, k, v, chi, clo);

    // --- output projection straight into d_out ---
    gemm_mma<0><<<gg, 256, GEMM_SMEM>>>(chi, clo,
        wthi + 3 * (size_t)DD * DD, wtlo + 3 * (size_t)DD * DD, bo, nullptr, out);
}